// round 16
// baseline (speedup 1.0000x reference)
#include <cuda_runtime.h>
#include <math_constants.h>
#include <math.h>
#include <cstdint>

#define TOKENS 16384
#define HIDDEN 7168
#define NEXP   256
#define TOPK   8
#define KC     32
#define NCH    (HIDDEN / KC)   // 224
#define TAU    2.5e-3f

// quantization: x = (h*128 + l) * S,  h,l in s8, bounds cover |a|<8, |w|<0.15
#define S_A  (8.0f    / 16256.0f)
#define S_B  (0.15f   / 16256.0f)
#define C1A  (1.0f / (128.0f * S_A))
#define C2A  (1.0f / S_A)
#define C1B  (1.0f / (128.0f * S_B))
#define C2B  (1.0f / S_B)
#define SC1  (16384.0f * S_A * S_B)   // weight of h*h accumulator
#define SC2  (128.0f   * S_A * S_B)   // weight of cross accumulator

// SMEM: 2 stages x {AH 4K | AL 4K | BH 4K | BL 4K} = 32KB static
#define ST     16384
#define OFF_AH 0
#define OFF_AL 4096
#define OFF_BH 8192
#define OFF_BL 12288

__device__ uint8_t g_B1[(size_t)NCH * NEXP * 32];   // hi plane, swizzle-baked
__device__ uint8_t g_B0[(size_t)NCH * NEXP * 32];   // lo plane
__device__ float   g_logits[(size_t)TOKENS * NEXP];
__device__ int     g_nflag;
__device__ int     g_flagged[TOKENS];

#define CPA16(dst, src) \
    asm volatile("cp.async.cg.shared.global [%0], [%1], 16;" \
                 :: "r"(dst), "l"(src) : "memory")

#define LDSM4(r, addr) \
    asm volatile("ldmatrix.sync.aligned.m8n8.x4.shared.b16 {%0,%1,%2,%3}, [%4];" \
                 : "=r"((r)[0]), "=r"((r)[1]), "=r"((r)[2]), "=r"((r)[3]) \
                 : "r"(addr))

#define MMA_S8(cp, a, B0r, B1r) \
    asm volatile("mma.sync.aligned.m16n8k32.row.col.s32.s8.s8.s32 " \
                 "{%0,%1,%2,%3},{%4,%5,%6,%7},{%8,%9},{%0,%1,%2,%3};" \
                 : "+r"((cp)[0]), "+r"((cp)[1]), "+r"((cp)[2]), "+r"((cp)[3]) \
                 : "r"((a)[0]), "r"((a)[1]), "r"((a)[2]), "r"((a)[3]), \
                   "r"(B0r), "r"(B1r))

// quantize one float -> (h, l) int pair
__device__ __forceinline__ void quant2(float v, float c1, float c2,
                                       int& h, int& l) {
    float hf = rintf(v * c1);
    hf = fminf(127.0f, fmaxf(-127.0f, hf));
    h = (int)hf;
    l = (int)rintf(fmaf(hf, -128.0f, v * c2));
}

__device__ __forceinline__ uint32_t pack4(int b0, int b1, int b2, int b3) {
    uint32_t p01 = __byte_perm((uint32_t)b0, (uint32_t)b1, 0x0040);
    uint32_t p23 = __byte_perm((uint32_t)b2, (uint32_t)b3, 0x0040);
    return __byte_perm(p01, p23, 0x5410);
}

// ---------------------------------------------------------------------------
// Kernel 0: split W fp32 -> 2-level s8, chunk-blocked [ch][n][32B], swizzled:
// 16B seg s stored at s ^ ((n>>2)&1).
// ---------------------------------------------------------------------------
__global__ __launch_bounds__(256)
void convert_b_kernel(const float* __restrict__ W) {
    if (blockIdx.x == 0 && threadIdx.x == 0) g_nflag = 0;

    const int ch = blockIdx.x;
    const int n  = threadIdx.x;
    const float* src = W + (size_t)n * HIDDEN + ch * KC;

    uint32_t hw[8], lw[8];
    #pragma unroll
    for (int g = 0; g < 8; g++) {
        float4 v = *(const float4*)(src + 4 * g);
        int h0, l0, h1, l1, h2, l2, h3, l3;
        quant2(v.x, C1B, C2B, h0, l0);
        quant2(v.y, C1B, C2B, h1, l1);
        quant2(v.z, C1B, C2B, h2, l2);
        quant2(v.w, C1B, C2B, h3, l3);
        hw[g] = pack4(h0, h1, h2, h3);
        lw[g] = pack4(l0, l1, l2, l3);
    }
    uint8_t* dh = g_B1 + ((size_t)ch * NEXP + n) * 32;
    uint8_t* dl = g_B0 + ((size_t)ch * NEXP + n) * 32;
    const int swn = (n >> 2) & 1;
    #pragma unroll
    for (int s = 0; s < 2; s++) {
        const int so = (s ^ swn) * 16;
        *(uint4*)(dh + so) = make_uint4(hw[4*s], hw[4*s+1], hw[4*s+2], hw[4*s+3]);
        *(uint4*)(dl + so) = make_uint4(lw[4*s], lw[4*s+1], lw[4*s+2], lw[4*s+3]);
    }
}

// ---------------------------------------------------------------------------
// Kernel 1: 2-level s8 GEMM via mma.m16n8k32.s8, 3 terms / 2 accumulators.
// CTA = 128 tokens x 128 experts, grid (128,2), 256 threads, 8 warps 4x2,
// warp tile 32x64.  logit = SC1*acc1 + SC2*acc2.
// ---------------------------------------------------------------------------
__global__ __launch_bounds__(256, 1)
void gemm_s8(const float* __restrict__ A)
{
    __shared__ char smem[2 * ST];
    uint32_t sb;
    asm("{ .reg .u64 t; cvta.to.shared.u64 t, %1; cvt.u32.u64 %0, t; }"
        : "=r"(sb) : "l"((void*)smem));

    const int tid  = threadIdx.x;
    const int lane = tid & 31;
    const int wid  = tid >> 5;
    const int wm   = wid >> 1;          // 0..3 (32-row band)
    const int wn   = wid & 1;           // 0..1 (64-col band)
    const int bm   = blockIdx.x * 128;
    const int bnb  = blockIdx.y * 128;

    // ldmatrix lane -> (row-in-16, 16B half)
    const int rowin = (lane & 7) + 8 * ((lane >> 3) & 1);
    const int half  = lane >> 4;

    // A loader: 8 thr/row, 4 passes of 32 rows
    const int arow = tid >> 3;          // 0..31 (+32p)
    const int aseg = (tid >> 2) & 1;    // 16B seg within row
    const int apos = tid & 3;           // word within seg
    const float* Agp = A + (size_t)(bm + arow) * HIDDEN + (tid & 7) * 4;

    // B loader: thread covers one n-row of one level (32B)
    const int blev = tid >> 7;          // 0 = hi, 1 = lo
    const int bn   = tid & 127;

    int acc1[2][8][4], acc2[2][8][4];
    #pragma unroll
    for (int i = 0; i < 2; i++)
        #pragma unroll
        for (int j = 0; j < 8; j++)
            #pragma unroll
            for (int q = 0; q < 4; q++) { acc1[i][j][q] = 0; acc2[i][j][q] = 0; }

#define LOAD_B_ASYNC(nc, st) do {                                              \
        const uint8_t* __gb = (blev ? g_B0 : g_B1) +                           \
            ((size_t)(nc) * NEXP + bnb + bn) * 32;                             \
        uint32_t __d = sb + (st) * ST + (blev ? OFF_BL : OFF_BH) + bn * 32;    \
        CPA16(__d,      __gb);                                                 \
        CPA16(__d + 16, __gb + 16);                                            \
        asm volatile("cp.async.commit_group;" ::: "memory");                   \
    } while (0)

#define LOAD_A_LDG(nc, av) do {                                                \
        _Pragma("unroll")                                                      \
        for (int p = 0; p < 4; p++)                                            \
            (av)[p] = __ldg((const float4*)(Agp + (size_t)(nc) * KC +          \
                                            (size_t)p * 32 * HIDDEN));         \
    } while (0)

#define STORE_A(st, av) do {                                                   \
        _Pragma("unroll")                                                      \
        for (int p = 0; p < 4; p++) {                                          \
            const int __row = arow + 32 * p;                                   \
            int h0,l0,h1,l1,h2,l2,h3,l3;                                       \
            quant2((av)[p].x, C1A, C2A, h0, l0);                               \
            quant2((av)[p].y, C1A, C2A, h1, l1);                               \
            quant2((av)[p].z, C1A, C2A, h2, l2);                               \
            quant2((av)[p].w, C1A, C2A, h3, l3);                               \
            uint32_t __hw = pack4(h0, h1, h2, h3);                             \
            uint32_t __lw = pack4(l0, l1, l2, l3);                             \
            uint32_t __ad = sb + (st) * ST + __row * 32 +                      \
                ((aseg ^ ((__row >> 2) & 1)) << 4) + apos * 4;                 \
            asm volatile("st.shared.u32 [%0], %1;"                             \
                         :: "r"(__ad + OFF_AH), "r"(__hw) : "memory");         \
            asm volatile("st.shared.u32 [%0], %1;"                             \
                         :: "r"(__ad + OFF_AL), "r"(__lw) : "memory");         \
        }                                                                      \
    } while (0)

    // ---- prologue ----
    {
        LOAD_B_ASYNC(0, 0);
        float4 av[4];
        LOAD_A_LDG(0, av);
        STORE_A(0, av);
        asm volatile("cp.async.wait_group 0;" ::: "memory");
        __syncthreads();
    }

    // ---- main loop ----
    for (int c = 0; c < NCH; c++) {
        const int s   = c & 1;
        const bool np = (c + 1 < NCH);
        float4 av[4];
        if (np) {
            LOAD_B_ASYNC(c + 1, s ^ 1);
            LOAD_A_LDG(c + 1, av);
        }

        const uint32_t base = sb + s * ST;
        uint32_t ah[2][4], al[2][4];
        #pragma unroll
        for (int mb = 0; mb < 2; mb++) {
            const int row = wm * 32 + mb * 16 + rowin;
            const uint32_t ad = base + row * 32 +
                                ((half ^ ((row >> 2) & 1)) << 4);
            LDSM4(ah[mb], ad + OFF_AH);
            LDSM4(al[mb], ad + OFF_AL);
        }
        #pragma unroll
        for (int g = 0; g < 4; g++) {
            const int nrow = wn * 64 + g * 16 + rowin;
            const uint32_t bd = base + nrow * 32 +
                                ((half ^ ((nrow >> 2) & 1)) << 4);
            uint32_t bh[4], bl[4];
            LDSM4(bh, bd + OFF_BH);
            LDSM4(bl, bd + OFF_BL);
            #pragma unroll
            for (int mb = 0; mb < 2; mb++) {
                MMA_S8(acc1[mb][2*g],     ah[mb], bh[0], bh[2]);
                MMA_S8(acc1[mb][2*g + 1], ah[mb], bh[1], bh[3]);
                MMA_S8(acc2[mb][2*g],     ah[mb], bl[0], bl[2]);
                MMA_S8(acc2[mb][2*g + 1], ah[mb], bl[1], bl[3]);
                MMA_S8(acc2[mb][2*g],     al[mb], bh[0], bh[2]);
                MMA_S8(acc2[mb][2*g + 1], al[mb], bh[1], bh[3]);
            }
        }

        if (np) {
            STORE_A(s ^ 1, av);
            asm volatile("cp.async.wait_group 0;" ::: "memory");
        }
        __syncthreads();
    }

    // ---- epilogue ----
    const int lq = lane >> 2;
    const int lr = lane & 3;
    #pragma unroll
    for (int mb = 0; mb < 2; mb++) {
        const int r0 = bm + wm * 32 + mb * 16 + lq;
        #pragma unroll
        for (int nb = 0; nb < 8; nb++) {
            const int col = bnb + wn * 64 + nb * 8 + 2 * lr;
            float f0 = (float)acc1[mb][nb][0] * SC1 + (float)acc2[mb][nb][0] * SC2;
            float f1 = (float)acc1[mb][nb][1] * SC1 + (float)acc2[mb][nb][1] * SC2;
            float f2 = (float)acc1[mb][nb][2] * SC1 + (float)acc2[mb][nb][2] * SC2;
            float f3 = (float)acc1[mb][nb][3] * SC1 + (float)acc2[mb][nb][3] * SC2;
            *(float2*)(g_logits + (size_t)r0 * NEXP + col)       = make_float2(f0, f1);
            *(float2*)(g_logits + (size_t)(r0 + 8) * NEXP + col) = make_float2(f2, f3);
        }
    }
}

// ---------------------------------------------------------------------------
// route_one: reference-exact routing for one token (validated R4-R15).
// ---------------------------------------------------------------------------
__device__ __forceinline__ void route_one(const float* __restrict__ row,
                                          const float* __restrict__ bias,
                                          float* __restrict__ out,
                                          int write_idx, int token, int lane,
                                          int do_flag)
{
    const unsigned FULL = 0xffffffffu;

    float4 l0 = *(const float4*)(row + lane * 8);
    float4 l1 = *(const float4*)(row + lane * 8 + 4);
    float4 b0 = *(const float4*)(bias + lane * 8);
    float4 b1 = *(const float4*)(bias + lane * 8 + 4);

    float lv[8] = {l0.x, l0.y, l0.z, l0.w, l1.x, l1.y, l1.z, l1.w};
    float bb[8] = {b0.x, b0.y, b0.z, b0.w, b1.x, b1.y, b1.z, b1.w};
    float sc[8], s4[8];
    #pragma unroll
    for (int i = 0; i < 8; i++) {
        float s = 1.0f / (1.0f + expf(-lv[i]));
        sc[i] = s;
        s4[i] = s + bb[i];
    }

    float m1 = -CUDART_INF_F, m2 = -CUDART_INF_F, m3 = -CUDART_INF_F;
    #pragma unroll
    for (int i = 0; i < 8; i++) {
        float v = s4[i];
        if (v > m1)      { m3 = m2; m2 = m1; m1 = v; }
        else if (v > m2) { m3 = m2; m2 = v; }
        else if (v > m3) { m3 = v; }
    }
    #pragma unroll
    for (int d = 1; d <= 2; d <<= 1) {
        float o1 = __shfl_xor_sync(FULL, m1, d);
        float o2 = __shfl_xor_sync(FULL, m2, d);
        float o3 = __shfl_xor_sync(FULL, m3, d);
        float mn1 = fminf(m1, o1);
        float mx2 = fmaxf(m2, o2);
        float n1 = fmaxf(m1, o1);
        float n2 = fmaxf(mn1, mx2);
        float n3 = fmaxf(fminf(mn1, mx2), fmaxf(m3, o3));
        m1 = n1; m2 = n2; m3 = n3;
    }
    const float gs  = m1 + m2;
    const float m23 = m2 - m3;
    const int   g   = lane >> 2;

    int rank = 0;
    #pragma unroll
    for (int j = 0; j < 8; j++) {
        float gj = __shfl_sync(FULL, gs, j * 4);
        rank += (gj > gs) || (gj == gs && j < g);
    }
    const int selg = (rank < 4);
    if (!selg) {
        #pragma unroll
        for (int i = 0; i < 8; i++) s4[i] = 0.0f;   // reference: score * mask
    }

    float flagmin = CUDART_INF_F;
    if (do_flag) {
        float vsel = selg ? gs : CUDART_INF_F;
        float vuns = selg ? -CUDART_INF_F : gs;
        float mm   = m23;
        #pragma unroll
        for (int d = 16; d; d >>= 1) {
            vsel = fminf(vsel, __shfl_xor_sync(FULL, vsel, d));
            vuns = fmaxf(vuns, __shfl_xor_sync(FULL, vuns, d));
            mm   = fminf(mm,   __shfl_xor_sync(FULL, mm,   d));
        }
        flagmin = fminf(vsel - vuns, mm);
    }

    float wsum = 0.0f, my_w = 0.0f, prevv = 0.0f;
    int   my_ix = 0;
    #pragma unroll
    for (int t = 0; t < 8; t++) {
        float bv = s4[0]; int bp = 0;
        #pragma unroll
        for (int i = 1; i < 8; i++)
            if (s4[i] > bv) { bv = s4[i]; bp = i; }
        float v  = bv;
        int   ix = lane * 8 + bp;
        #pragma unroll
        for (int d = 16; d; d >>= 1) {
            float ov = __shfl_xor_sync(FULL, v, d);
            int   oi = __shfl_xor_sync(FULL, ix, d);
            if (ov > v || (ov == v && oi < ix)) { v = ov; ix = oi; }
        }
        if (t > 0) flagmin = fminf(flagmin, prevv - v);
        prevv = v;
        const int opos  = ix & 7;
        const int olane = ix >> 3;
        #pragma unroll
        for (int i = 0; i < 8; i++)
            if (lane == olane && i == opos) s4[i] = -CUDART_INF_F;
        float cand = sc[0];
        #pragma unroll
        for (int i = 1; i < 8; i++)
            if (i == opos) cand = sc[i];
        float w = __shfl_sync(FULL, cand, olane);
        wsum += w;
        if (lane == t) { my_w = w; my_ix = ix; }
    }

    if (do_flag) {
        float bv = s4[0];
        #pragma unroll
        for (int i = 1; i < 8; i++) bv = fmaxf(bv, s4[i]);
        #pragma unroll
        for (int d = 16; d; d >>= 1)
            bv = fmaxf(bv, __shfl_xor_sync(FULL, bv, d));
        flagmin = fminf(flagmin, prevv - bv);
        if (lane == 0 && flagmin < TAU) {
            int p = atomicAdd(&g_nflag, 1);
            g_flagged[p] = token;
        }
    }

    const float scale = 2.5f / (wsum + 1e-20f);
    if (lane < TOPK) {
        out[(size_t)token * TOPK + lane] = my_w * scale;
        if (write_idx)
            out[(size_t)TOKENS * TOPK + (size_t)token * TOPK + lane] = (float)my_ix;
    }
}

// ---------------------------------------------------------------------------
__global__ __launch_bounds__(256)
void routing_kernel(const float* __restrict__ bias, float* __restrict__ out,
                    int write_idx)
{
    const int lane  = threadIdx.x & 31;
    const int warp  = threadIdx.x >> 5;
    const int token = blockIdx.x * 8 + warp;
    route_one(g_logits + (size_t)token * NEXP, bias, out, write_idx, token,
              lane, 1);
}

// ---------------------------------------------------------------------------
__global__ __launch_bounds__(256)
void recompute_kernel(const float* __restrict__ A, const float* __restrict__ W,
                      const float* __restrict__ bias, float* __restrict__ out,
                      int write_idx)
{
    __shared__ __align__(16) float srow[HIDDEN];
    __shared__ __align__(16) float slog[NEXP];

    const int nf   = g_nflag;
    const int wid  = threadIdx.x >> 5;
    const int lane = threadIdx.x & 31;

    for (int it = blockIdx.x; it < nf; it += gridDim.x) {
        const int token = g_flagged[it];
        for (int i = threadIdx.x * 4; i < HIDDEN; i += 1024)
            *(float4*)(srow + i) = *(const float4*)(A + (size_t)token * HIDDEN + i);
        __syncthreads();

        for (int e = wid * 32; e < wid * 32 + 32; e++) {
            const float* wr = W + (size_t)e * HIDDEN;
            float a0 = 0.f, a1 = 0.f;
            for (int i = lane * 4; i < HIDDEN; i += 256) {
                float4 wv = *(const float4*)(wr + i);
                float4 av = *(const float4*)(srow + i);
                a0 += av.x * wv.x + av.y * wv.y + av.z * wv.z + av.w * wv.w;
                float4 wv2 = *(const float4*)(wr + i + 128);
                float4 av2 = *(const float4*)(srow + i + 128);
                a1 += av2.x * wv2.x + av2.y * wv2.y + av2.z * wv2.z + av2.w * wv2.w;
            }
            float acc = a0 + a1;
            #pragma unroll
            for (int d = 16; d; d >>= 1)
                acc += __shfl_xor_sync(0xffffffffu, acc, d);
            if (lane == 0) slog[e] = acc;
        }
        __syncthreads();

        if (wid == 0)
            route_one(slog, bias, out, write_idx, token, lane, 0);
        __syncthreads();
    }
}

// ---------------------------------------------------------------------------
extern "C" void kernel_launch(void* const* d_in, const int* in_sizes, int n_in,
                              void* d_out, int out_size)
{
    const float* hs   = (const float*)d_in[0];  // [16384, 7168]
    const float* w    = (const float*)d_in[1];  // [256, 7168]
    const float* bias = (const float*)d_in[2];  // [256]
    float* out = (float*)d_out;

    const int write_idx = (out_size >= TOKENS * TOPK * 2) ? 1 : 0;

    convert_b_kernel<<<NCH, 256>>>(w);
    dim3 ggrid(TOKENS / 128, 2);
    gemm_s8<<<ggrid, 256>>>(hs);
    routing_kernel<<<TOKENS / 8, 256>>>(bias, out, write_idx);
    recompute_kernel<<<128, 256>>>(hs, w, bias, out, write_idx);
}

// round 17
// speedup vs baseline: 1.2087x; 1.2087x over previous
#include <cuda_runtime.h>
#include <cuda_fp16.h>
#include <math_constants.h>
#include <math.h>
#include <cstdint>

#define TOKENS 16384
#define HIDDEN 7168
#define NEXP   256
#define TOPK   8
#define KC     32
#define NCH    (HIDDEN / KC)   // 224
#define TAU    2e-3f

// SMEM per stage: Ah 8K | Al 8K | Bh 16K = 32KB
#define ST_BYTES 32768
#define OFF_AH   0
#define OFF_AL   8192
#define OFF_BH   16384
#define SMEM_TOTAL (2 * ST_BYTES)

// chunk-blocked swizzle-baked f16 weights: [ch][n][64B]
__device__ uint32_t g_Bh[(size_t)NEXP * HIDDEN / 2];
__device__ float    g_logits[(size_t)TOKENS * NEXP];
__device__ int      g_nflag;
__device__ int      g_flagged[TOKENS];

__device__ __forceinline__ uint32_t pack_h2(float lo, float hi) {
    __half2 t = __floats2half2_rn(lo, hi);   // x = lo (low half)
    return *reinterpret_cast<uint32_t*>(&t);
}

#define CPA16(dst, src) \
    asm volatile("cp.async.cg.shared.global [%0], [%1], 16;" \
                 :: "r"(dst), "l"(src) : "memory")

#define LDSM4(r, addr) \
    asm volatile("ldmatrix.sync.aligned.m8n8.x4.shared.b16 {%0,%1,%2,%3}, [%4];" \
                 : "=r"((r)[0]), "=r"((r)[1]), "=r"((r)[2]), "=r"((r)[3]) \
                 : "r"(addr))

#define MMA_F16(cp, a, B0, B1) \
    asm volatile("mma.sync.aligned.m16n8k16.row.col.f32.f16.f16.f32 " \
                 "{%0,%1,%2,%3},{%4,%5,%6,%7},{%8,%9},{%0,%1,%2,%3};" \
                 : "+f"((cp)[0]), "+f"((cp)[1]), "+f"((cp)[2]), "+f"((cp)[3]) \
                 : "r"((a)[0]), "r"((a)[1]), "r"((a)[2]), "r"((a)[3]), \
                   "r"(B0), "r"(B1))

// ---------------------------------------------------------------------------
// Kernel 0: W fp32 -> f16 (single plane), chunk-blocked + swizzle baked
// (same layout as the validated R7/R14 converter: 64B row, seg s^((n>>1)&3)).
// ---------------------------------------------------------------------------
__global__ __launch_bounds__(256)
void convert_b_kernel(const float* __restrict__ W) {
    if (blockIdx.x == 0 && threadIdx.x == 0) g_nflag = 0;

    const int ch = blockIdx.x;
    const int n  = threadIdx.x;
    const float* src = W + (size_t)n * HIDDEN + ch * KC;

    float v[32];
    #pragma unroll
    for (int j = 0; j < 8; j++) {
        float4 t = *(const float4*)(src + 4 * j);
        v[4 * j] = t.x; v[4 * j + 1] = t.y; v[4 * j + 2] = t.z; v[4 * j + 3] = t.w;
    }
    uint32_t hw[16];
    #pragma unroll
    for (int k = 0; k < 16; k++)
        hw[k] = pack_h2(v[2 * k], v[2 * k + 1]);

    char* dh = (char*)g_Bh + (size_t)ch * (NEXP * 64) + n * 64;
    const int swn = (n >> 1) & 3;
    #pragma unroll
    for (int s = 0; s < 4; s++) {
        const int so = (s ^ swn) * 16;
        *(uint4*)(dh + so) = make_uint4(hw[4*s], hw[4*s+1], hw[4*s+2], hw[4*s+3]);
    }
}

// ---------------------------------------------------------------------------
// Kernel 1: 2-term f16-split GEMM (R14's machinery, bf16->f16, 3->2 terms).
// One 512-thread CTA (16 warps 4x4, warp tile 32x64), grid 128 single wave.
// logits = (Ah + Al) * Bh, fp32 accum.
// ---------------------------------------------------------------------------
__global__ __launch_bounds__(512, 1)
void gemm_f16(const float* __restrict__ A)
{
    extern __shared__ char smem[];
    uint32_t sb;
    asm("{ .reg .u64 t; cvta.to.shared.u64 t, %1; cvt.u32.u64 %0, t; }"
        : "=r"(sb) : "l"((void*)smem));

    const int tid  = threadIdx.x;
    const int lane = tid & 31;
    const int wid  = tid >> 5;
    const int wm   = wid >> 2;          // 0..3 (32-row band)
    const int wn   = wid & 3;           // 0..3 (64-col band)
    const int bm   = blockIdx.x * 128;

    // ldmatrix lane address components (identical to R14)
    const int rowin = ((lane >> 3) & 1) * 8 + (lane & 7);
    const int kqa   = lane >> 4;
    const int swa   = (rowin >> 1) & 3;
    const int nin   = ((lane >> 4) & 1) * 8 + (lane & 7);
    const int kqb   = (lane >> 3) & 1;
    const int swb   = (nin >> 1) & 3;
    const uint32_t arowoff = (uint32_t)(wm * 32 + rowin) * 64;
    const uint32_t browoff = (uint32_t)(wn * 64 + nin) * 64;

    // A loader: 4 threads/row, 8 k each
    const int arow  = tid >> 2;         // 0..127
    const int apart = tid & 3;          // k octet
    const int swr   = (arow >> 1) & 3;
    const float* Agp = A + (size_t)(bm + arow) * HIDDEN + apart * 8;
    // B loader: 2 threads/row, 32B each (hi plane only)
    const int brow  = tid >> 1;         // 0..255
    const int bhalf = tid & 1;

    float cc[2][8][4];
    #pragma unroll
    for (int i = 0; i < 2; i++)
        #pragma unroll
        for (int j = 0; j < 8; j++)
            #pragma unroll
            for (int q = 0; q < 4; q++) cc[i][j][q] = 0.0f;

#define LOAD_B_ASYNC(nc, st) do {                                              \
        const char* __sh = (const char*)g_Bh + (size_t)(nc) * (NEXP * 64)      \
                           + brow * 64 + bhalf * 32;                           \
        uint32_t __dh = sb + (st) * ST_BYTES + OFF_BH + brow * 64 + bhalf * 32;\
        CPA16(__dh,      __sh);                                                \
        CPA16(__dh + 16, __sh + 16);                                           \
        asm volatile("cp.async.commit_group;" ::: "memory");                   \
    } while (0)

#define LOAD_A_LDG(nc, va) do {                                                \
        const float* __p = Agp + (size_t)(nc) * KC;                            \
        float4 t0 = __ldg((const float4*)__p);                                 \
        float4 t1 = __ldg((const float4*)(__p + 4));                           \
        (va)[0] = t0.x; (va)[1] = t0.y; (va)[2] = t0.z; (va)[3] = t0.w;        \
        (va)[4] = t1.x; (va)[5] = t1.y; (va)[6] = t1.z; (va)[7] = t1.w;        \
    } while (0)

#define STORE_A(st, va) do {                                                   \
        uint32_t h[4], l[4];                                                   \
        _Pragma("unroll")                                                      \
        for (int k = 0; k < 4; k++) {                                          \
            float a0 = (va)[2*k], a1 = (va)[2*k+1];                            \
            __half h0 = __float2half_rn(a0);                                   \
            __half h1 = __float2half_rn(a1);                                   \
            h[k] = pack_h2(__half2float(h0), __half2float(h1));                \
            l[k] = pack_h2(a0 - __half2float(h0), a1 - __half2float(h1));      \
        }                                                                      \
        const uint32_t __off = (st) * ST_BYTES + arow * 64 +                   \
                               ((apart ^ swr) << 4);                           \
        *(uint4*)(smem + __off + OFF_AH) = make_uint4(h[0], h[1], h[2], h[3]); \
        *(uint4*)(smem + __off + OFF_AL) = make_uint4(l[0], l[1], l[2], l[3]); \
    } while (0)

    // ---- prologue ----
    {
        LOAD_B_ASYNC(0, 0);
        float va[8];
        LOAD_A_LDG(0, va);
        STORE_A(0, va);
        asm volatile("cp.async.wait_group 0;" ::: "memory");
        __syncthreads();
    }

    // ---- main loop ----
    for (int c = 0; c < NCH; c++) {
        const int s   = c & 1;
        const bool np = (c + 1 < NCH);
        float va[8];
        if (np) {
            LOAD_B_ASYNC(c + 1, s ^ 1);
            LOAD_A_LDG(c + 1, va);
        }

        const uint32_t base = sb + s * ST_BYTES;
        #pragma unroll
        for (int H = 0; H < 2; H++) {
            const uint32_t aseg = (uint32_t)((((H << 1) | kqa) ^ swa) * 16);
            const uint32_t bseg = (uint32_t)((((H << 1) | kqb) ^ swb) * 16);
            uint32_t ah[2][4], al[2][4], bf[4][4];
            #pragma unroll
            for (int mb = 0; mb < 2; mb++)
                LDSM4(ah[mb], base + OFF_AH + arowoff + mb * 1024 + aseg);
            #pragma unroll
            for (int pr = 0; pr < 4; pr++)
                LDSM4(bf[pr], base + OFF_BH + browoff + pr * 1024 + bseg);
            #pragma unroll
            for (int mb = 0; mb < 2; mb++)
                #pragma unroll
                for (int pr = 0; pr < 4; pr++) {
                    MMA_F16(cc[mb][2*pr],     ah[mb], bf[pr][0], bf[pr][1]);
                    MMA_F16(cc[mb][2*pr + 1], ah[mb], bf[pr][2], bf[pr][3]);
                }
            #pragma unroll
            for (int mb = 0; mb < 2; mb++)
                LDSM4(al[mb], base + OFF_AL + arowoff + mb * 1024 + aseg);
            #pragma unroll
            for (int mb = 0; mb < 2; mb++)
                #pragma unroll
                for (int pr = 0; pr < 4; pr++) {
                    MMA_F16(cc[mb][2*pr],     al[mb], bf[pr][0], bf[pr][1]);
                    MMA_F16(cc[mb][2*pr + 1], al[mb], bf[pr][2], bf[pr][3]);
                }
        }

        if (np) {
            STORE_A(s ^ 1, va);
            asm volatile("cp.async.wait_group 0;" ::: "memory");
        }
        __syncthreads();
    }

    // ---- epilogue ----
    const int lq = lane >> 2;
    const int lr = lane & 3;
    #pragma unroll
    for (int mb = 0; mb < 2; mb++) {
        const int r0 = bm + wm * 32 + mb * 16 + lq;
        #pragma unroll
        for (int nb = 0; nb < 8; nb++) {
            const int col = wn * 64 + nb * 8 + 2 * lr;
            *(float2*)(g_logits + (size_t)r0 * NEXP + col) =
                make_float2(cc[mb][nb][0], cc[mb][nb][1]);
            *(float2*)(g_logits + (size_t)(r0 + 8) * NEXP + col) =
                make_float2(cc[mb][nb][2], cc[mb][nb][3]);
        }
    }
}

// ---------------------------------------------------------------------------
// route_one: reference-exact routing for one token (validated R4-R16).
// ---------------------------------------------------------------------------
__device__ __forceinline__ void route_one(const float* __restrict__ row,
                                          const float* __restrict__ bias,
                                          float* __restrict__ out,
                                          int write_idx, int token, int lane,
                                          int do_flag)
{
    const unsigned FULL = 0xffffffffu;

    float4 l0 = *(const float4*)(row + lane * 8);
    float4 l1 = *(const float4*)(row + lane * 8 + 4);
    float4 b0 = *(const float4*)(bias + lane * 8);
    float4 b1 = *(const float4*)(bias + lane * 8 + 4);

    float lv[8] = {l0.x, l0.y, l0.z, l0.w, l1.x, l1.y, l1.z, l1.w};
    float bb[8] = {b0.x, b0.y, b0.z, b0.w, b1.x, b1.y, b1.z, b1.w};
    float sc[8], s4[8];
    #pragma unroll
    for (int i = 0; i < 8; i++) {
        float s = 1.0f / (1.0f + expf(-lv[i]));
        sc[i] = s;
        s4[i] = s + bb[i];
    }

    float m1 = -CUDART_INF_F, m2 = -CUDART_INF_F, m3 = -CUDART_INF_F;
    #pragma unroll
    for (int i = 0; i < 8; i++) {
        float v = s4[i];
        if (v > m1)      { m3 = m2; m2 = m1; m1 = v; }
        else if (v > m2) { m3 = m2; m2 = v; }
        else if (v > m3) { m3 = v; }
    }
    #pragma unroll
    for (int d = 1; d <= 2; d <<= 1) {
        float o1 = __shfl_xor_sync(FULL, m1, d);
        float o2 = __shfl_xor_sync(FULL, m2, d);
        float o3 = __shfl_xor_sync(FULL, m3, d);
        float mn1 = fminf(m1, o1);
        float mx2 = fmaxf(m2, o2);
        float n1 = fmaxf(m1, o1);
        float n2 = fmaxf(mn1, mx2);
        float n3 = fmaxf(fminf(mn1, mx2), fmaxf(m3, o3));
        m1 = n1; m2 = n2; m3 = n3;
    }
    const float gs  = m1 + m2;
    const float m23 = m2 - m3;
    const int   g   = lane >> 2;

    int rank = 0;
    #pragma unroll
    for (int j = 0; j < 8; j++) {
        float gj = __shfl_sync(FULL, gs, j * 4);
        rank += (gj > gs) || (gj == gs && j < g);
    }
    const int selg = (rank < 4);
    if (!selg) {
        #pragma unroll
        for (int i = 0; i < 8; i++) s4[i] = 0.0f;   // reference: score * mask
    }

    float flagmin = CUDART_INF_F;
    if (do_flag) {
        float vsel = selg ? gs : CUDART_INF_F;
        float vuns = selg ? -CUDART_INF_F : gs;
        float mm   = m23;
        #pragma unroll
        for (int d = 16; d; d >>= 1) {
            vsel = fminf(vsel, __shfl_xor_sync(FULL, vsel, d));
            vuns = fmaxf(vuns, __shfl_xor_sync(FULL, vuns, d));
            mm   = fminf(mm,   __shfl_xor_sync(FULL, mm,   d));
        }
        flagmin = fminf(vsel - vuns, mm);
    }

    float wsum = 0.0f, my_w = 0.0f, prevv = 0.0f;
    int   my_ix = 0;
    #pragma unroll
    for (int t = 0; t < 8; t++) {
        float bv = s4[0]; int bp = 0;
        #pragma unroll
        for (int i = 1; i < 8; i++)
            if (s4[i] > bv) { bv = s4[i]; bp = i; }
        float v  = bv;
        int   ix = lane * 8 + bp;
        #pragma unroll
        for (int d = 16; d; d >>= 1) {
            float ov = __shfl_xor_sync(FULL, v, d);
            int   oi = __shfl_xor_sync(FULL, ix, d);
            if (ov > v || (ov == v && oi < ix)) { v = ov; ix = oi; }
        }
        if (t > 0) flagmin = fminf(flagmin, prevv - v);
        prevv = v;
        const int opos  = ix & 7;
        const int olane = ix >> 3;
        #pragma unroll
        for (int i = 0; i < 8; i++)
            if (lane == olane && i == opos) s4[i] = -CUDART_INF_F;
        float cand = sc[0];
        #pragma unroll
        for (int i = 1; i < 8; i++)
            if (i == opos) cand = sc[i];
        float w = __shfl_sync(FULL, cand, olane);
        wsum += w;
        if (lane == t) { my_w = w; my_ix = ix; }
    }

    if (do_flag) {
        float bv = s4[0];
        #pragma unroll
        for (int i = 1; i < 8; i++) bv = fmaxf(bv, s4[i]);
        #pragma unroll
        for (int d = 16; d; d >>= 1)
            bv = fmaxf(bv, __shfl_xor_sync(FULL, bv, d));
        flagmin = fminf(flagmin, prevv - bv);
        if (lane == 0 && flagmin < TAU) {
            int p = atomicAdd(&g_nflag, 1);
            g_flagged[p] = token;
        }
    }

    const float scale = 2.5f / (wsum + 1e-20f);
    if (lane < TOPK) {
        out[(size_t)token * TOPK + lane] = my_w * scale;
        if (write_idx)
            out[(size_t)TOKENS * TOPK + (size_t)token * TOPK + lane] = (float)my_ix;
    }
}

// ---------------------------------------------------------------------------
__global__ __launch_bounds__(256)
void routing_kernel(const float* __restrict__ bias, float* __restrict__ out,
                    int write_idx)
{
    const int lane  = threadIdx.x & 31;
    const int warp  = threadIdx.x >> 5;
    const int token = blockIdx.x * 8 + warp;
    route_one(g_logits + (size_t)token * NEXP, bias, out, write_idx, token,
              lane, 1);
}

// ---------------------------------------------------------------------------
__global__ __launch_bounds__(256)
void recompute_kernel(const float* __restrict__ A, const float* __restrict__ W,
                      const float* __restrict__ bias, float* __restrict__ out,
                      int write_idx)
{
    __shared__ __align__(16) float srow[HIDDEN];
    __shared__ __align__(16) float slog[NEXP];

    const int nf   = g_nflag;
    const int wid  = threadIdx.x >> 5;
    const int lane = threadIdx.x & 31;

    for (int it = blockIdx.x; it < nf; it += gridDim.x) {
        const int token = g_flagged[it];
        for (int i = threadIdx.x * 4; i < HIDDEN; i += 1024)
            *(float4*)(srow + i) = *(const float4*)(A + (size_t)token * HIDDEN + i);
        __syncthreads();

        for (int e = wid * 32; e < wid * 32 + 32; e++) {
            const float* wr = W + (size_t)e * HIDDEN;
            float a0 = 0.f, a1 = 0.f;
            for (int i = lane * 4; i < HIDDEN; i += 256) {
                float4 wv = *(const float4*)(wr + i);
                float4 av = *(const float4*)(srow + i);
                a0 += av.x * wv.x + av.y * wv.y + av.z * wv.z + av.w * wv.w;
                float4 wv2 = *(const float4*)(wr + i + 128);
                float4 av2 = *(const float4*)(srow + i + 128);
                a1 += av2.x * wv2.x + av2.y * wv2.y + av2.z * wv2.z + av2.w * wv2.w;
            }
            float acc = a0 + a1;
            #pragma unroll
            for (int d = 16; d; d >>= 1)
                acc += __shfl_xor_sync(0xffffffffu, acc, d);
            if (lane == 0) slog[e] = acc;
        }
        __syncthreads();

        if (wid == 0)
            route_one(slog, bias, out, write_idx, token, lane, 0);
        __syncthreads();
    }
}

// ---------------------------------------------------------------------------
extern "C" void kernel_launch(void* const* d_in, const int* in_sizes, int n_in,
                              void* d_out, int out_size)
{
    const float* hs   = (const float*)d_in[0];  // [16384, 7168]
    const float* w    = (const float*)d_in[1];  // [256, 7168]
    const float* bias = (const float*)d_in[2];  // [256]
    float* out = (float*)d_out;

    cudaFuncSetAttribute(gemm_f16,
                         cudaFuncAttributeMaxDynamicSharedMemorySize,
                         SMEM_TOTAL);

    const int write_idx = (out_size >= TOKENS * TOPK * 2) ? 1 : 0;

    convert_b_kernel<<<NCH, 256>>>(w);
    gemm_f16<<<TOKENS / 128, 512, SMEM_TOTAL>>>(hs);
    routing_kernel<<<TOKENS / 8, 256>>>(bias, out, write_idx);
    recompute_kernel<<<128, 256>>>(hs, w, bias, out, write_idx);
}